// round 12
// baseline (speedup 1.0000x reference)
#include <cuda_runtime.h>
#include <cuda_fp16.h>
#include <cstdint>

// ---------------------------------------------------------------------------
// W4A16 grouped-quant linear: Y[M,N] = X[M,K] @ dequant(Wpacked)[K,N]
//  M=8192, K=4096, N=11008, group=128
//  Harness: x/scales/zeros float32, weight_packed int32, out float32;
//  compute_103 virtual target (no tcgen05) -> legacy mma.sync HMMA path.
//  K0 (fused): x f32->fp16 g_X  +  dequant int4->fp16 g_W[K][N]
//  K1: 128x128x32 GEMM (R10-proven mainloop: wait -> sync -> loads -> compute),
//      4 warps (64x64), 4-stage cp.async, 2 CTAs/SM, f32 accum, f32 out.
//  NOTE (learned R11): cp.async completion is per-thread; the per-thread
//  cp_wait MUST precede the __syncthreads that publishes smem to other warps.
// ---------------------------------------------------------------------------

namespace {
constexpr int Mdim = 8192;
constexpr int Kdim = 4096;
constexpr int Ndim = 11008;
constexpr int GRP  = 128;

constexpr int BM = 128, BN = 128, BK = 32;
constexpr int STAGES = 4;
constexpr int ASTRIDE = BK + 8;     // 40 halves
constexpr int BSTRIDE = BN + 8;     // 136 halves
constexpr int TM = Mdim / BM;       // 64
constexpr int TN = Ndim / BN;       // 86
constexpr int KT = Kdim / BK;       // 128
constexpr int GROUP_M = 16;
constexpr int SMEM_BYTES = STAGES * (BM * ASTRIDE + BK * BSTRIDE) * 2; // 75776

// fused pre-pass block ranges
constexpr int XBLOCKS = (Mdim * Kdim / 4) / 256;                  // 32768
constexpr int WBLOCKS = ((Kdim / 2) * (Ndim / 4)) / 256;          // 22016
}

// Static device scratch (no cudaMalloc allowed).
__device__ __align__(16) __half g_W[(size_t)Kdim * (size_t)Ndim];  // 90 MB
__device__ __align__(16) __half g_X[(size_t)Mdim * (size_t)Kdim];  // 64 MB

// ---------------------------------------------------------------------------
// PTX helpers
// ---------------------------------------------------------------------------
__device__ __forceinline__ uint32_t smem_u32(const void* p) {
    return (uint32_t)__cvta_generic_to_shared(p);
}
__device__ __forceinline__ void cp_async16(uint32_t s, const void* g) {
    asm volatile("cp.async.cg.shared.global [%0], [%1], 16;\n" :: "r"(s), "l"(g));
}
__device__ __forceinline__ void cp_commit() {
    asm volatile("cp.async.commit_group;\n");
}
template <int N>
__device__ __forceinline__ void cp_wait() {
    asm volatile("cp.async.wait_group %0;\n" :: "n"(N));
}
__device__ __forceinline__ void ldsm_x4(uint32_t addr, uint32_t& r0, uint32_t& r1,
                                        uint32_t& r2, uint32_t& r3) {
    asm volatile("ldmatrix.sync.aligned.m8n8.x4.shared.b16 {%0,%1,%2,%3}, [%4];\n"
                 : "=r"(r0), "=r"(r1), "=r"(r2), "=r"(r3) : "r"(addr));
}
__device__ __forceinline__ void ldsm_x4t(uint32_t addr, uint32_t& r0, uint32_t& r1,
                                         uint32_t& r2, uint32_t& r3) {
    asm volatile("ldmatrix.sync.aligned.m8n8.x4.trans.shared.b16 {%0,%1,%2,%3}, [%4];\n"
                 : "=r"(r0), "=r"(r1), "=r"(r2), "=r"(r3) : "r"(addr));
}
__device__ __forceinline__ void mma16816(float& c0, float& c1, float& c2, float& c3,
                                         uint32_t a0, uint32_t a1, uint32_t a2, uint32_t a3,
                                         uint32_t b0, uint32_t b1) {
    asm volatile("mma.sync.aligned.m16n8k16.row.col.f32.f16.f16.f32 "
                 "{%0,%1,%2,%3}, {%4,%5,%6,%7}, {%8,%9}, {%0,%1,%2,%3};\n"
                 : "+f"(c0), "+f"(c1), "+f"(c2), "+f"(c3)
                 : "r"(a0), "r"(a1), "r"(a2), "r"(a3), "r"(b0), "r"(b1));
}

// ---------------------------------------------------------------------------
// Kernel 0 (fused pre-pass): blocks [0,XBLOCKS) convert x f32->fp16;
// blocks [XBLOCKS, XBLOCKS+WBLOCKS) dequantize packed int4 -> fp16 g_W.
// Both tasks are independent and memory-bound; fusing overlaps their streams.
// ---------------------------------------------------------------------------
__global__ void prepass_kernel(const float* __restrict__ xf,
                               const int* __restrict__ wp,
                               const float* __restrict__ scales,
                               const float* __restrict__ zeros) {
    if (blockIdx.x < XBLOCKS) {
        // --- convert x (exact fp16 values; lossless) ---
        size_t i = ((size_t)blockIdx.x * 256 + threadIdx.x) * 4;
        float4 v = *(const float4*)(xf + i);
        __align__(8) __half h[4];
        h[0] = __float2half_rn(v.x); h[1] = __float2half_rn(v.y);
        h[2] = __float2half_rn(v.z); h[3] = __float2half_rn(v.w);
        *(uint2*)(g_X + i) = *(uint2*)h;
        return;
    }
    // --- dequant (verified R5 logic) ---
    constexpr int KH = Kdim / 2;            // 2048
    constexpr int PER_ROW = Ndim / 4;       // 2752
    size_t idx = (size_t)(blockIdx.x - XBLOCKS) * 256 + threadIdx.x;
    if (idx >= (size_t)KH * PER_ROW) return;

    int kk = (int)(idx / PER_ROW);
    int n4 = (int)(idx % PER_ROW) * 4;

    int4 p = *(const int4*)(wp + (size_t)kk * Ndim + n4);
    int g0 = kk / GRP;
    int g1 = g0 + KH / GRP;

    float4 s0 = *(const float4*)(scales + (size_t)g0 * Ndim + n4);
    float4 z0 = *(const float4*)(zeros  + (size_t)g0 * Ndim + n4);
    float4 s1 = *(const float4*)(scales + (size_t)g1 * Ndim + n4);
    float4 z1 = *(const float4*)(zeros  + (size_t)g1 * Ndim + n4);

    int   pv[4] = {p.x, p.y, p.z, p.w};
    float s0a[4] = {s0.x, s0.y, s0.z, s0.w};
    float z0a[4] = {z0.x, z0.y, z0.z, z0.w};
    float s1a[4] = {s1.x, s1.y, s1.z, s1.w};
    float z1a[4] = {z1.x, z1.y, z1.z, z1.w};

    __align__(8) __half lo[4];
    __align__(8) __half hi[4];
#pragma unroll
    for (int i = 0; i < 4; i++) {
        int ql = pv[i] & 0xF;
        int qh = (pv[i] >> 4) & 0xF;
        lo[i] = __hmul(__hsub(__int2half_rn(ql), __float2half_rn(z0a[i])),
                       __float2half_rn(s0a[i]));
        hi[i] = __hmul(__hsub(__int2half_rn(qh), __float2half_rn(z1a[i])),
                       __float2half_rn(s1a[i]));
    }
    *(uint2*)(g_W + (size_t)kk * Ndim + n4)        = *(uint2*)lo;
    *(uint2*)(g_W + (size_t)(kk + KH) * Ndim + n4) = *(uint2*)hi;
}

// ---------------------------------------------------------------------------
// Kernel 1: fp16 GEMM, CTA 128x128x32, 4 warps (2x2), warp tile 64x64,
// 4-stage cp.async, single barrier per K-iteration, 2 CTAs/SM.
// Proven R10 ordering: wait(kt) -> sync -> issue loads(kt+3) -> compute(kt).
// ---------------------------------------------------------------------------
__global__ void __launch_bounds__(128, 2) w4a16_gemm(float* __restrict__ Y) {
    extern __shared__ __half smem[];
    __half* As = smem;                                  // STAGES * BM * ASTRIDE
    __half* Bs = smem + STAGES * BM * ASTRIDE;          // STAGES * BK * BSTRIDE

    const int tid  = threadIdx.x;
    const int lane = tid & 31;
    const int warp = tid >> 5;
    const int wm   = (warp >> 1) * 64;   // 0 / 64
    const int wn   = (warp & 1) * 64;    // 0 / 64

    // L2-friendly rasterization
    int pid = blockIdx.x;
    int per_group = GROUP_M * TN;
    int group = pid / per_group;
    int rem = pid - group * per_group;
    int pm = group * GROUP_M + (rem % GROUP_M);
    int pn = rem / GROUP_M;
    const int m0 = pm * BM;
    const int n0 = pn * BN;

    const uint32_t as_u32 = smem_u32(As);
    const uint32_t bs_u32 = smem_u32(Bs);

    float acc[4][8][4];
#pragma unroll
    for (int i = 0; i < 4; i++)
#pragma unroll
        for (int j = 0; j < 8; j++)
#pragma unroll
            for (int k = 0; k < 4; k++) acc[i][j][k] = 0.f;

    auto load_tile = [&](int st, int kt) {
        const __half* gA0 = g_X + (size_t)m0 * Kdim + (size_t)kt * BK;
        const __half* gB0 = g_W + (size_t)kt * BK * Ndim + n0;
        uint32_t sa = as_u32 + st * BM * ASTRIDE * 2;
        uint32_t sb = bs_u32 + st * BK * BSTRIDE * 2;
#pragma unroll
        for (int i = 0; i < 4; i++) {          // A: 512 16B chunks, 128 threads
            int c = tid + i * 128;
            int ar = c >> 2, acl = (c & 3) << 3;
            cp_async16(sa + (ar * ASTRIDE + acl) * 2, gA0 + (size_t)ar * Kdim + acl);
        }
#pragma unroll
        for (int i = 0; i < 4; i++) {          // B: 512 16B chunks
            int c = tid + i * 128;
            int br = c >> 4, bcl = (c & 15) << 3;
            cp_async16(sb + (br * BSTRIDE + bcl) * 2, gB0 + (size_t)br * Ndim + bcl);
        }
    };

#pragma unroll
    for (int s = 0; s < STAGES - 1; s++) { load_tile(s, s); cp_commit(); }

    for (int kt = 0; kt < KT; kt++) {
        // Per-thread drain FIRST (committed = 3+kt; tile kt retired <=>
        // pending <= 2), THEN the barrier publishes all threads' copies.
        cp_wait<2>();
        __syncthreads();

        // Issue loads for tile kt+3 into buffer (kt+3)%4 (read in iter kt-1;
        // safe: every warp passed the sync only after finishing iter kt-1).
        int lt = kt + STAGES - 1;
        if (lt < KT) load_tile(lt % STAGES, lt);
        cp_commit();                  // keeps committed count = 3+kt+1

        int st = kt % STAGES;
        uint32_t sa_st = as_u32 + st * BM * ASTRIDE * 2;
        uint32_t sb_st = bs_u32 + st * BK * BSTRIDE * 2;

#pragma unroll
        for (int ks = 0; ks < 2; ks++) {   // two k16 steps per BK=32
            uint32_t a[4][4];
            uint32_t b[4][4];
#pragma unroll
            for (int mf = 0; mf < 4; mf++) {
                uint32_t addr = sa_st +
                    ((wm + mf * 16 + (lane & 15)) * ASTRIDE + ks * 16 + (lane >> 4) * 8) * 2;
                ldsm_x4(addr, a[mf][0], a[mf][1], a[mf][2], a[mf][3]);
            }
#pragma unroll
            for (int nf2 = 0; nf2 < 4; nf2++) {
                uint32_t addr = sb_st +
                    ((ks * 16 + (lane & 15)) * BSTRIDE + wn + nf2 * 16 + (lane >> 4) * 8) * 2;
                ldsm_x4t(addr, b[nf2][0], b[nf2][1], b[nf2][2], b[nf2][3]);
            }
#pragma unroll
            for (int mf = 0; mf < 4; mf++)
#pragma unroll
                for (int nf = 0; nf < 8; nf++)
                    mma16816(acc[mf][nf][0], acc[mf][nf][1], acc[mf][nf][2], acc[mf][nf][3],
                             a[mf][0], a[mf][1], a[mf][2], a[mf][3],
                             b[nf >> 1][(nf & 1) * 2], b[nf >> 1][(nf & 1) * 2 + 1]);
        }
    }

    // Epilogue: f32 accum -> fp16 round -> f32 store.
#pragma unroll
    for (int mf = 0; mf < 4; mf++) {
        int row = m0 + wm + mf * 16 + (lane >> 2);
#pragma unroll
        for (int nf = 0; nf < 8; nf++) {
            int col = n0 + wn + nf * 8 + (lane & 3) * 2;
            float v0 = __half2float(__float2half_rn(acc[mf][nf][0]));
            float v1 = __half2float(__float2half_rn(acc[mf][nf][1]));
            float v2 = __half2float(__float2half_rn(acc[mf][nf][2]));
            float v3 = __half2float(__float2half_rn(acc[mf][nf][3]));
            *(float2*)(Y + (size_t)row * Ndim + col)       = make_float2(v0, v1);
            *(float2*)(Y + (size_t)(row + 8) * Ndim + col) = make_float2(v2, v3);
        }
    }
}

// ---------------------------------------------------------------------------
// Launch. Inputs bound BY ELEMENT COUNT:
//   x: 33,554,432 f32 | weight_packed: 22,544,384 i32 | scales/zeros: 352,256 f32
// Output: float32 [M,N].
// ---------------------------------------------------------------------------
extern "C" void kernel_launch(void* const* d_in, const int* in_sizes, int n_in,
                              void* d_out, int out_size) {
    const float* x  = nullptr;
    const int*   wp = nullptr;
    const float* sc = nullptr;
    const float* zr = nullptr;
    for (int i = 0; i < n_in; i++) {
        long sz = in_sizes[i];
        if (sz == (long)Mdim * Kdim)            x  = (const float*)d_in[i];
        else if (sz == (long)(Kdim / 2) * Ndim) wp = (const int*)d_in[i];
        else if (sz == (long)(Kdim / GRP) * Ndim) {
            if (!sc) sc = (const float*)d_in[i];
            else     zr = (const float*)d_in[i];
        }
    }
    float* y = (float*)d_out;

    // 0) fused pre-pass: convert x + dequant W (independent, overlapped)
    prepass_kernel<<<XBLOCKS + WBLOCKS, 256>>>(x, wp, sc, zr);

    // 1) fp16 tensor-core GEMM -> f32 output
    cudaFuncSetAttribute(w4a16_gemm, cudaFuncAttributeMaxDynamicSharedMemorySize, SMEM_BYTES);
    w4a16_gemm<<<TM * TN, 128, SMEM_BYTES>>>(y);
}

// round 13
// speedup vs baseline: 1.2998x; 1.2998x over previous
#include <cuda_runtime.h>
#include <cuda_fp16.h>
#include <cstdint>

// ---------------------------------------------------------------------------
// W4A16 grouped-quant linear: Y[M,N] = X[M,K] @ dequant(Wpacked)[K,N]
//  M=8192, K=4096, N=11008, group=128
//  Harness: x/scales/zeros float32, weight_packed int32, out float32;
//  compute_103 virtual target (no tcgen05) -> legacy mma.sync HMMA path.
//  K0: x f32 -> fp16 g_X          (separate launches: fusion regressed in R12)
//  K1: dequant int4 -> fp16 g_W[K][N]
//  K2: 128x128x64 GEMM, 4 warps (64x64), 3-stage cp.async, 2 CTAs/SM,
//      R10-proven ordering (wait -> sync -> issue loads -> compute),
//      64 K-iterations (halved boundary bubbles vs BK=32).
//  Learned: cp.async completion is per-thread; cp_wait must precede the
//  __syncthreads that publishes smem (R11). Loads must be issued >=1 full
//  iteration before their wait or the load latency is exposed (R9).
// ---------------------------------------------------------------------------

namespace {
constexpr int Mdim = 8192;
constexpr int Kdim = 4096;
constexpr int Ndim = 11008;
constexpr int GRP  = 128;

constexpr int BM = 128, BN = 128, BK = 64;
constexpr int STAGES = 3;
constexpr int ASTRIDE = BK + 8;     // 72 halves (144B rows; 144%128=16 -> conflict-free)
constexpr int BSTRIDE = BN + 8;     // 136 halves
constexpr int TM = Mdim / BM;       // 64
constexpr int TN = Ndim / BN;       // 86
constexpr int KT = Kdim / BK;       // 64
constexpr int GROUP_M = 16;
constexpr int SMEM_BYTES = STAGES * (BM * ASTRIDE + BK * BSTRIDE) * 2; // 107520
}

// Static device scratch (no cudaMalloc allowed).
__device__ __align__(16) __half g_W[(size_t)Kdim * (size_t)Ndim];  // 90 MB
__device__ __align__(16) __half g_X[(size_t)Mdim * (size_t)Kdim];  // 64 MB

// ---------------------------------------------------------------------------
// PTX helpers
// ---------------------------------------------------------------------------
__device__ __forceinline__ uint32_t smem_u32(const void* p) {
    return (uint32_t)__cvta_generic_to_shared(p);
}
__device__ __forceinline__ void cp_async16(uint32_t s, const void* g) {
    asm volatile("cp.async.cg.shared.global [%0], [%1], 16;\n" :: "r"(s), "l"(g));
}
__device__ __forceinline__ void cp_commit() {
    asm volatile("cp.async.commit_group;\n");
}
template <int N>
__device__ __forceinline__ void cp_wait() {
    asm volatile("cp.async.wait_group %0;\n" :: "n"(N));
}
__device__ __forceinline__ void ldsm_x4(uint32_t addr, uint32_t& r0, uint32_t& r1,
                                        uint32_t& r2, uint32_t& r3) {
    asm volatile("ldmatrix.sync.aligned.m8n8.x4.shared.b16 {%0,%1,%2,%3}, [%4];\n"
                 : "=r"(r0), "=r"(r1), "=r"(r2), "=r"(r3) : "r"(addr));
}
__device__ __forceinline__ void ldsm_x4t(uint32_t addr, uint32_t& r0, uint32_t& r1,
                                         uint32_t& r2, uint32_t& r3) {
    asm volatile("ldmatrix.sync.aligned.m8n8.x4.trans.shared.b16 {%0,%1,%2,%3}, [%4];\n"
                 : "=r"(r0), "=r"(r1), "=r"(r2), "=r"(r3) : "r"(addr));
}
__device__ __forceinline__ void mma16816(float& c0, float& c1, float& c2, float& c3,
                                         uint32_t a0, uint32_t a1, uint32_t a2, uint32_t a3,
                                         uint32_t b0, uint32_t b1) {
    asm volatile("mma.sync.aligned.m16n8k16.row.col.f32.f16.f16.f32 "
                 "{%0,%1,%2,%3}, {%4,%5,%6,%7}, {%8,%9}, {%0,%1,%2,%3};\n"
                 : "+f"(c0), "+f"(c1), "+f"(c2), "+f"(c3)
                 : "r"(a0), "r"(a1), "r"(a2), "r"(a3), "r"(b0), "r"(b1));
}

// ---------------------------------------------------------------------------
// Kernel 0: x float32 -> fp16 (lossless)
// ---------------------------------------------------------------------------
__global__ void convert_x_kernel(const float* __restrict__ xf) {
    size_t i = ((size_t)blockIdx.x * blockDim.x + threadIdx.x) * 4;
    if (i >= (size_t)Mdim * Kdim) return;
    float4 v = *(const float4*)(xf + i);
    __align__(8) __half h[4];
    h[0] = __float2half_rn(v.x); h[1] = __float2half_rn(v.y);
    h[2] = __float2half_rn(v.z); h[3] = __float2half_rn(v.w);
    *(uint2*)(g_X + i) = *(uint2*)h;
}

// ---------------------------------------------------------------------------
// Kernel 1: dequantize packed int4 -> fp16 g_W[K][N] (verified R5)
// ---------------------------------------------------------------------------
__global__ void dequant_kernel(const int* __restrict__ wp,
                               const float* __restrict__ scales,
                               const float* __restrict__ zeros) {
    constexpr int KH = Kdim / 2;            // 2048
    constexpr int PER_ROW = Ndim / 4;       // 2752
    size_t idx = (size_t)blockIdx.x * blockDim.x + threadIdx.x;
    if (idx >= (size_t)KH * PER_ROW) return;

    int kk = (int)(idx / PER_ROW);
    int n4 = (int)(idx % PER_ROW) * 4;

    int4 p = *(const int4*)(wp + (size_t)kk * Ndim + n4);
    int g0 = kk / GRP;
    int g1 = g0 + KH / GRP;

    float4 s0 = *(const float4*)(scales + (size_t)g0 * Ndim + n4);
    float4 z0 = *(const float4*)(zeros  + (size_t)g0 * Ndim + n4);
    float4 s1 = *(const float4*)(scales + (size_t)g1 * Ndim + n4);
    float4 z1 = *(const float4*)(zeros  + (size_t)g1 * Ndim + n4);

    int   pv[4] = {p.x, p.y, p.z, p.w};
    float s0a[4] = {s0.x, s0.y, s0.z, s0.w};
    float z0a[4] = {z0.x, z0.y, z0.z, z0.w};
    float s1a[4] = {s1.x, s1.y, s1.z, s1.w};
    float z1a[4] = {z1.x, z1.y, z1.z, z1.w};

    __align__(8) __half lo[4];
    __align__(8) __half hi[4];
#pragma unroll
    for (int i = 0; i < 4; i++) {
        int ql = pv[i] & 0xF;
        int qh = (pv[i] >> 4) & 0xF;
        lo[i] = __hmul(__hsub(__int2half_rn(ql), __float2half_rn(z0a[i])),
                       __float2half_rn(s0a[i]));
        hi[i] = __hmul(__hsub(__int2half_rn(qh), __float2half_rn(z1a[i])),
                       __float2half_rn(s1a[i]));
    }
    *(uint2*)(g_W + (size_t)kk * Ndim + n4)        = *(uint2*)lo;
    *(uint2*)(g_W + (size_t)(kk + KH) * Ndim + n4) = *(uint2*)hi;
}

// ---------------------------------------------------------------------------
// Kernel 2: fp16 GEMM, CTA 128x128x64, 4 warps (2x2), warp tile 64x64,
// 3-stage cp.async, single barrier per K-iteration, 2 CTAs/SM.
// Order: wait(kt) -> sync -> issue loads(kt+2) -> compute(kt).
// Tile kt+2's load gets ~2 full iterations of compute cover before its wait.
// ---------------------------------------------------------------------------
__global__ void __launch_bounds__(128, 2) w4a16_gemm(float* __restrict__ Y) {
    extern __shared__ __half smem[];
    __half* As = smem;                                  // STAGES * BM * ASTRIDE
    __half* Bs = smem + STAGES * BM * ASTRIDE;          // STAGES * BK * BSTRIDE

    const int tid  = threadIdx.x;
    const int lane = tid & 31;
    const int warp = tid >> 5;
    const int wm   = (warp >> 1) * 64;   // 0 / 64
    const int wn   = (warp & 1) * 64;    // 0 / 64

    // L2-friendly rasterization
    int pid = blockIdx.x;
    int per_group = GROUP_M * TN;
    int group = pid / per_group;
    int rem = pid - group * per_group;
    int pm = group * GROUP_M + (rem % GROUP_M);
    int pn = rem / GROUP_M;
    const int m0 = pm * BM;
    const int n0 = pn * BN;

    const uint32_t as_u32 = smem_u32(As);
    const uint32_t bs_u32 = smem_u32(Bs);

    float acc[4][8][4];
#pragma unroll
    for (int i = 0; i < 4; i++)
#pragma unroll
        for (int j = 0; j < 8; j++)
#pragma unroll
            for (int k = 0; k < 4; k++) acc[i][j][k] = 0.f;

    auto load_tile = [&](int st, int kt) {
        const __half* gA0 = g_X + (size_t)m0 * Kdim + (size_t)kt * BK;
        const __half* gB0 = g_W + (size_t)kt * BK * Ndim + n0;
        uint32_t sa = as_u32 + st * BM * ASTRIDE * 2;
        uint32_t sb = bs_u32 + st * BK * BSTRIDE * 2;
#pragma unroll
        for (int i = 0; i < 8; i++) {          // A: 1024 16B chunks, 128 threads
            int c = tid + i * 128;
            int ar = c >> 3, acl = (c & 7) << 3;
            cp_async16(sa + (ar * ASTRIDE + acl) * 2, gA0 + (size_t)ar * Kdim + acl);
        }
#pragma unroll
        for (int i = 0; i < 8; i++) {          // B: 1024 16B chunks
            int c = tid + i * 128;
            int br = c >> 4, bcl = (c & 15) << 3;
            cp_async16(sb + (br * BSTRIDE + bcl) * 2, gB0 + (size_t)br * Ndim + bcl);
        }
    };

    load_tile(0, 0); cp_commit();
    load_tile(1, 1); cp_commit();

    for (int kt = 0; kt < KT; kt++) {
        // Committed groups = 2 + kt (prologue 2 + one per prior iteration).
        // Tile kt retired <=> pending <= 1 (only tile kt+1 may be in flight).
        // Per-thread drain BEFORE the publishing barrier (R11 lesson).
        cp_wait<1>();
        __syncthreads();

        // Issue loads for tile kt+2 into buffer (kt+2)%3 (= (kt-1)%3, read in
        // iter kt-1; safe — all warps passed the sync after finishing kt-1).
        int lt = kt + STAGES - 1;
        if (lt < KT) load_tile(lt % STAGES, lt);
        cp_commit();                  // keeps committed count = 2+kt+1

        int st = kt % STAGES;
        uint32_t sa_st = as_u32 + st * BM * ASTRIDE * 2;
        uint32_t sb_st = bs_u32 + st * BK * BSTRIDE * 2;

#pragma unroll
        for (int ks = 0; ks < 4; ks++) {   // four k16 steps per BK=64
            uint32_t a[4][4];
            uint32_t b[4][4];
#pragma unroll
            for (int mf = 0; mf < 4; mf++) {
                uint32_t addr = sa_st +
                    ((wm + mf * 16 + (lane & 15)) * ASTRIDE + ks * 16 + (lane >> 4) * 8) * 2;
                ldsm_x4(addr, a[mf][0], a[mf][1], a[mf][2], a[mf][3]);
            }
#pragma unroll
            for (int nf2 = 0; nf2 < 4; nf2++) {
                uint32_t addr = sb_st +
                    ((ks * 16 + (lane & 15)) * BSTRIDE + wn + nf2 * 16 + (lane >> 4) * 8) * 2;
                ldsm_x4t(addr, b[nf2][0], b[nf2][1], b[nf2][2], b[nf2][3]);
            }
#pragma unroll
            for (int mf = 0; mf < 4; mf++)
#pragma unroll
                for (int nf = 0; nf < 8; nf++)
                    mma16816(acc[mf][nf][0], acc[mf][nf][1], acc[mf][nf][2], acc[mf][nf][3],
                             a[mf][0], a[mf][1], a[mf][2], a[mf][3],
                             b[nf >> 1][(nf & 1) * 2], b[nf >> 1][(nf & 1) * 2 + 1]);
        }
    }

    // Epilogue: f32 accum -> fp16 round -> f32 store.
#pragma unroll
    for (int mf = 0; mf < 4; mf++) {
        int row = m0 + wm + mf * 16 + (lane >> 2);
#pragma unroll
        for (int nf = 0; nf < 8; nf++) {
            int col = n0 + wn + nf * 8 + (lane & 3) * 2;
            float v0 = __half2float(__float2half_rn(acc[mf][nf][0]));
            float v1 = __half2float(__float2half_rn(acc[mf][nf][1]));
            float v2 = __half2float(__float2half_rn(acc[mf][nf][2]));
            float v3 = __half2float(__float2half_rn(acc[mf][nf][3]));
            *(float2*)(Y + (size_t)row * Ndim + col)       = make_float2(v0, v1);
            *(float2*)(Y + (size_t)(row + 8) * Ndim + col) = make_float2(v2, v3);
        }
    }
}

// ---------------------------------------------------------------------------
// Launch. Inputs bound BY ELEMENT COUNT:
//   x: 33,554,432 f32 | weight_packed: 22,544,384 i32 | scales/zeros: 352,256 f32
// Output: float32 [M,N].
// ---------------------------------------------------------------------------
extern "C" void kernel_launch(void* const* d_in, const int* in_sizes, int n_in,
                              void* d_out, int out_size) {
    const float* x  = nullptr;
    const int*   wp = nullptr;
    const float* sc = nullptr;
    const float* zr = nullptr;
    for (int i = 0; i < n_in; i++) {
        long sz = in_sizes[i];
        if (sz == (long)Mdim * Kdim)            x  = (const float*)d_in[i];
        else if (sz == (long)(Kdim / 2) * Ndim) wp = (const int*)d_in[i];
        else if (sz == (long)(Kdim / GRP) * Ndim) {
            if (!sc) sc = (const float*)d_in[i];
            else     zr = (const float*)d_in[i];
        }
    }
    float* y = (float*)d_out;

    {
        size_t quads = (size_t)Mdim * Kdim / 4;
        convert_x_kernel<<<(int)((quads + 255) / 256), 256>>>(x);
    }
    {
        size_t total = (size_t)(Kdim / 2) * (Ndim / 4);
        dequant_kernel<<<(int)((total + 255) / 256), 256>>>(wp, sc, zr);
    }
    cudaFuncSetAttribute(w4a16_gemm, cudaFuncAttributeMaxDynamicSharedMemorySize, SMEM_BYTES);
    w4a16_gemm<<<TM * TN, 128, SMEM_BYTES>>>(y);
}

// round 14
// speedup vs baseline: 1.6198x; 1.2462x over previous
#include <cuda_runtime.h>
#include <cuda_fp16.h>
#include <cstdint>

// ---------------------------------------------------------------------------
// W4A16 grouped-quant linear: Y[M,N] = X[M,K] @ dequant(Wpacked)[K,N]
//  M=8192, K=4096, N=11008, group=128
//  Harness: x/scales/zeros float32, weight_packed int32, out float32;
//  compute_103 virtual target (no tcgen05) -> legacy mma.sync HMMA path.
//  K0: x f32 -> fp16 g_X
//  K1: dequant int4 -> fp16 g_W[K][N]
//  K2: 128x128x32 GEMM (R10 geometry: 4 warps 64x64, 4-stage cp.async,
//      2 CTAs/SM, wait->sync->loads->compute) + REGISTER DOUBLE-BUFFERED
//      ldmatrix fragments (ks+1 frags issued under ks's MMA shadow).
//  Learned: cp_wait precedes the publishing barrier (R11); loads issued >=1
//  iter ahead (R9); BK=64/3-stage regresses (R9,R13); fusion regresses (R12).
// ---------------------------------------------------------------------------

namespace {
constexpr int Mdim = 8192;
constexpr int Kdim = 4096;
constexpr int Ndim = 11008;
constexpr int GRP  = 128;

constexpr int BM = 128, BN = 128, BK = 32;
constexpr int STAGES = 4;
constexpr int ASTRIDE = BK + 8;     // 40 halves
constexpr int BSTRIDE = BN + 8;     // 136 halves
constexpr int TM = Mdim / BM;       // 64
constexpr int TN = Ndim / BN;       // 86
constexpr int KT = Kdim / BK;       // 128
constexpr int GROUP_M = 16;
constexpr int SMEM_BYTES = STAGES * (BM * ASTRIDE + BK * BSTRIDE) * 2; // 75776
}

// Static device scratch (no cudaMalloc allowed).
__device__ __align__(16) __half g_W[(size_t)Kdim * (size_t)Ndim];  // 90 MB
__device__ __align__(16) __half g_X[(size_t)Mdim * (size_t)Kdim];  // 64 MB

// ---------------------------------------------------------------------------
// PTX helpers
// ---------------------------------------------------------------------------
__device__ __forceinline__ uint32_t smem_u32(const void* p) {
    return (uint32_t)__cvta_generic_to_shared(p);
}
__device__ __forceinline__ void cp_async16(uint32_t s, const void* g) {
    asm volatile("cp.async.cg.shared.global [%0], [%1], 16;\n" :: "r"(s), "l"(g));
}
__device__ __forceinline__ void cp_commit() {
    asm volatile("cp.async.commit_group;\n");
}
template <int N>
__device__ __forceinline__ void cp_wait() {
    asm volatile("cp.async.wait_group %0;\n" :: "n"(N));
}
__device__ __forceinline__ void ldsm_x4(uint32_t addr, uint32_t& r0, uint32_t& r1,
                                        uint32_t& r2, uint32_t& r3) {
    asm volatile("ldmatrix.sync.aligned.m8n8.x4.shared.b16 {%0,%1,%2,%3}, [%4];\n"
                 : "=r"(r0), "=r"(r1), "=r"(r2), "=r"(r3) : "r"(addr));
}
__device__ __forceinline__ void ldsm_x4t(uint32_t addr, uint32_t& r0, uint32_t& r1,
                                         uint32_t& r2, uint32_t& r3) {
    asm volatile("ldmatrix.sync.aligned.m8n8.x4.trans.shared.b16 {%0,%1,%2,%3}, [%4];\n"
                 : "=r"(r0), "=r"(r1), "=r"(r2), "=r"(r3) : "r"(addr));
}
__device__ __forceinline__ void mma16816(float& c0, float& c1, float& c2, float& c3,
                                         uint32_t a0, uint32_t a1, uint32_t a2, uint32_t a3,
                                         uint32_t b0, uint32_t b1) {
    asm volatile("mma.sync.aligned.m16n8k16.row.col.f32.f16.f16.f32 "
                 "{%0,%1,%2,%3}, {%4,%5,%6,%7}, {%8,%9}, {%0,%1,%2,%3};\n"
                 : "+f"(c0), "+f"(c1), "+f"(c2), "+f"(c3)
                 : "r"(a0), "r"(a1), "r"(a2), "r"(a3), "r"(b0), "r"(b1));
}

// ---------------------------------------------------------------------------
// Kernel 0: x float32 -> fp16 (lossless)
// ---------------------------------------------------------------------------
__global__ void convert_x_kernel(const float* __restrict__ xf) {
    size_t i = ((size_t)blockIdx.x * blockDim.x + threadIdx.x) * 4;
    if (i >= (size_t)Mdim * Kdim) return;
    float4 v = *(const float4*)(xf + i);
    __align__(8) __half h[4];
    h[0] = __float2half_rn(v.x); h[1] = __float2half_rn(v.y);
    h[2] = __float2half_rn(v.z); h[3] = __float2half_rn(v.w);
    *(uint2*)(g_X + i) = *(uint2*)h;
}

// ---------------------------------------------------------------------------
// Kernel 1: dequantize packed int4 -> fp16 g_W[K][N] (verified R5)
// ---------------------------------------------------------------------------
__global__ void dequant_kernel(const int* __restrict__ wp,
                               const float* __restrict__ scales,
                               const float* __restrict__ zeros) {
    constexpr int KH = Kdim / 2;            // 2048
    constexpr int PER_ROW = Ndim / 4;       // 2752
    size_t idx = (size_t)blockIdx.x * blockDim.x + threadIdx.x;
    if (idx >= (size_t)KH * PER_ROW) return;

    int kk = (int)(idx / PER_ROW);
    int n4 = (int)(idx % PER_ROW) * 4;

    int4 p = *(const int4*)(wp + (size_t)kk * Ndim + n4);
    int g0 = kk / GRP;
    int g1 = g0 + KH / GRP;

    float4 s0 = *(const float4*)(scales + (size_t)g0 * Ndim + n4);
    float4 z0 = *(const float4*)(zeros  + (size_t)g0 * Ndim + n4);
    float4 s1 = *(const float4*)(scales + (size_t)g1 * Ndim + n4);
    float4 z1 = *(const float4*)(zeros  + (size_t)g1 * Ndim + n4);

    int   pv[4] = {p.x, p.y, p.z, p.w};
    float s0a[4] = {s0.x, s0.y, s0.z, s0.w};
    float z0a[4] = {z0.x, z0.y, z0.z, z0.w};
    float s1a[4] = {s1.x, s1.y, s1.z, s1.w};
    float z1a[4] = {z1.x, z1.y, z1.z, z1.w};

    __align__(8) __half lo[4];
    __align__(8) __half hi[4];
#pragma unroll
    for (int i = 0; i < 4; i++) {
        int ql = pv[i] & 0xF;
        int qh = (pv[i] >> 4) & 0xF;
        lo[i] = __hmul(__hsub(__int2half_rn(ql), __float2half_rn(z0a[i])),
                       __float2half_rn(s0a[i]));
        hi[i] = __hmul(__hsub(__int2half_rn(qh), __float2half_rn(z1a[i])),
                       __float2half_rn(s1a[i]));
    }
    *(uint2*)(g_W + (size_t)kk * Ndim + n4)        = *(uint2*)lo;
    *(uint2*)(g_W + (size_t)(kk + KH) * Ndim + n4) = *(uint2*)hi;
}

// ---------------------------------------------------------------------------
// Kernel 2: fp16 GEMM, CTA 128x128x32, 4 warps (2x2), warp tile 64x64,
// 4-stage cp.async, single barrier/iter, 2 CTAs/SM, reg-double-buffered frags.
// ---------------------------------------------------------------------------
__global__ void __launch_bounds__(128, 2) w4a16_gemm(float* __restrict__ Y) {
    extern __shared__ __half smem[];
    __half* As = smem;                                  // STAGES * BM * ASTRIDE
    __half* Bs = smem + STAGES * BM * ASTRIDE;          // STAGES * BK * BSTRIDE

    const int tid  = threadIdx.x;
    const int lane = tid & 31;
    const int warp = tid >> 5;
    const int wm   = (warp >> 1) * 64;   // 0 / 64
    const int wn   = (warp & 1) * 64;    // 0 / 64

    // L2-friendly rasterization
    int pid = blockIdx.x;
    int per_group = GROUP_M * TN;
    int group = pid / per_group;
    int rem = pid - group * per_group;
    int pm = group * GROUP_M + (rem % GROUP_M);
    int pn = rem / GROUP_M;
    const int m0 = pm * BM;
    const int n0 = pn * BN;

    const uint32_t as_u32 = smem_u32(As);
    const uint32_t bs_u32 = smem_u32(Bs);

    float acc[4][8][4];
#pragma unroll
    for (int i = 0; i < 4; i++)
#pragma unroll
        for (int j = 0; j < 8; j++)
#pragma unroll
            for (int k = 0; k < 4; k++) acc[i][j][k] = 0.f;

    auto load_tile = [&](int st, int kt) {
        const __half* gA0 = g_X + (size_t)m0 * Kdim + (size_t)kt * BK;
        const __half* gB0 = g_W + (size_t)kt * BK * Ndim + n0;
        uint32_t sa = as_u32 + st * BM * ASTRIDE * 2;
        uint32_t sb = bs_u32 + st * BK * BSTRIDE * 2;
#pragma unroll
        for (int i = 0; i < 4; i++) {          // A: 512 16B chunks, 128 threads
            int c = tid + i * 128;
            int ar = c >> 2, acl = (c & 3) << 3;
            cp_async16(sa + (ar * ASTRIDE + acl) * 2, gA0 + (size_t)ar * Kdim + acl);
        }
#pragma unroll
        for (int i = 0; i < 4; i++) {          // B: 512 16B chunks
            int c = tid + i * 128;
            int br = c >> 4, bcl = (c & 15) << 3;
            cp_async16(sb + (br * BSTRIDE + bcl) * 2, gB0 + (size_t)br * Ndim + bcl);
        }
    };

    // fragment loaders (ks selects the k16 half of the BK=32 tile)
    uint32_t a[2][4][4];
    uint32_t b[2][4][4];
    auto load_frags = [&](int buf, uint32_t sa_st, uint32_t sb_st, int ks) {
#pragma unroll
        for (int mf = 0; mf < 4; mf++) {
            uint32_t addr = sa_st +
                ((wm + mf * 16 + (lane & 15)) * ASTRIDE + ks * 16 + (lane >> 4) * 8) * 2;
            ldsm_x4(addr, a[buf][mf][0], a[buf][mf][1], a[buf][mf][2], a[buf][mf][3]);
        }
#pragma unroll
        for (int nf2 = 0; nf2 < 4; nf2++) {
            uint32_t addr = sb_st +
                ((ks * 16 + (lane & 15)) * BSTRIDE + wn + nf2 * 16 + (lane >> 4) * 8) * 2;
            ldsm_x4t(addr, b[buf][nf2][0], b[buf][nf2][1], b[buf][nf2][2], b[buf][nf2][3]);
        }
    };
    auto mma_block = [&](int buf) {
#pragma unroll
        for (int mf = 0; mf < 4; mf++)
#pragma unroll
            for (int nf = 0; nf < 8; nf++)
                mma16816(acc[mf][nf][0], acc[mf][nf][1], acc[mf][nf][2], acc[mf][nf][3],
                         a[buf][mf][0], a[buf][mf][1], a[buf][mf][2], a[buf][mf][3],
                         b[buf][nf >> 1][(nf & 1) * 2], b[buf][nf >> 1][(nf & 1) * 2 + 1]);
    };

#pragma unroll
    for (int s = 0; s < STAGES - 1; s++) { load_tile(s, s); cp_commit(); }

    for (int kt = 0; kt < KT; kt++) {
        // Per-thread drain FIRST (tile kt retired <=> pending <= 2), THEN the
        // barrier publishes all threads' copies (R11 lesson).
        cp_wait<2>();
        __syncthreads();

        // Issue gmem loads for tile kt+3 (buffer read in iter kt-1; safe).
        int lt = kt + STAGES - 1;
        if (lt < KT) load_tile(lt % STAGES, lt);
        cp_commit();

        int st = kt % STAGES;
        uint32_t sa_st = as_u32 + st * BM * ASTRIDE * 2;
        uint32_t sb_st = bs_u32 + st * BK * BSTRIDE * 2;

        // Software-pipelined fragments: ldsm(ks1) issues under mma(ks0)'s shadow.
        load_frags(0, sa_st, sb_st, 0);
        load_frags(1, sa_st, sb_st, 1);
        mma_block(0);
        mma_block(1);
    }

    // Epilogue: f32 accum -> fp16 round -> f32 store.
#pragma unroll
    for (int mf = 0; mf < 4; mf++) {
        int row = m0 + wm + mf * 16 + (lane >> 2);
#pragma unroll
        for (int nf = 0; nf < 8; nf++) {
            int col = n0 + wn + nf * 8 + (lane & 3) * 2;
            float v0 = __half2float(__float2half_rn(acc[mf][nf][0]));
            float v1 = __half2float(__float2half_rn(acc[mf][nf][1]));
            float v2 = __half2float(__float2half_rn(acc[mf][nf][2]));
            float v3 = __half2float(__float2half_rn(acc[mf][nf][3]));
            *(float2*)(Y + (size_t)row * Ndim + col)       = make_float2(v0, v1);
            *(float2*)(Y + (size_t)(row + 8) * Ndim + col) = make_float2(v2, v3);
        }
    }
}

// ---------------------------------------------------------------------------
// Launch. Inputs bound BY ELEMENT COUNT:
//   x: 33,554,432 f32 | weight_packed: 22,544,384 i32 | scales/zeros: 352,256 f32
// Output: float32 [M,N].
// ---------------------------------------------------------------------------
extern "C" void kernel_launch(void* const* d_in, const int* in_sizes, int n_in,
                              void* d_out, int out_size) {
    const float* x  = nullptr;
    const int*   wp = nullptr;
    const float* sc = nullptr;
    const float* zr = nullptr;
    for (int i = 0; i < n_in; i++) {
        long sz = in_sizes[i];
        if (sz == (long)Mdim * Kdim)            x  = (const float*)d_in[i];
        else if (sz == (long)(Kdim / 2) * Ndim) wp = (const int*)d_in[i];
        else if (sz == (long)(Kdim / GRP) * Ndim) {
            if (!sc) sc = (const float*)d_in[i];
            else     zr = (const float*)d_in[i];
        }
    }
    float* y = (float*)d_out;

    {
        size_t quads = (size_t)Mdim * Kdim / 4;
        convert_x_kernel<<<(int)((quads + 255) / 256), 256>>>(x);
    }
    {
        size_t total = (size_t)(Kdim / 2) * (Ndim / 4);
        dequant_kernel<<<(int)((total + 255) / 256), 256>>>(wp, sc, zr);
    }
    cudaFuncSetAttribute(w4a16_gemm, cudaFuncAttributeMaxDynamicSharedMemorySize, SMEM_BYTES);
    w4a16_gemm<<<TM * TN, 128, SMEM_BYTES>>>(y);
}